// round 5
// baseline (speedup 1.0000x reference)
#include <cuda_runtime.h>
#include <math.h>

// DBI_44985487458968 — Davies-Bouldin index.
// N=2M points x D=64 f32, K=100 clusters, scalar f32 out.
//
// Single pass over data accumulating per-cluster {count, sum[64], sum||x||^2},
// then a tiny finalize kernel computes centroids, Si via the expansion
//   Sum||x-A||^2 = Sxx - 2 A.Sx + n ||A||^2,
// pairwise centroid distances, Rij row-maxes, and the DBI scalar.
//
// Robustness: input binding resolved from element counts (points = 64x ids);
// clustering dtype (int32 vs int64 — JAX x64 default makes int64 requests
// silently int32) resolved by a device-side probe of the odd 32-bit words.

#define KC   100
#define DF   64
#define NSUM (KC * DF)          // 6400 centroid-sum accumulators
#define NACC (NSUM + 2 * KC)    // + counts + sumsq = 6600

__device__ float g_acc[NACC];   // scratch (no cudaMalloc allowed)
__device__ int   g_id64;        // 1 if clustering is int64, 0 if int32

// ------------------------------------------------------- init + probe ----
__global__ void dbi_init_kernel(const unsigned int* __restrict__ cl_u32, int n) {
    int i = blockIdx.x * blockDim.x + threadIdx.x;
    if (i < NACC) g_acc[i] = 0.0f;
    if (i == 0) {
        // If ids are int64 (values < 100), every odd u32 word is 0.
        // For int32 ids the odd words are ids themselves; P(128 zeros) ~ 0.
        int nprobe = n < 128 ? n : 128;
        int any_nonzero = 0;
        for (int k = 0; k < nprobe; k++)
            any_nonzero |= (cl_u32[2 * k + 1] != 0u);
        g_id64 = !any_nonzero;
    }
}

// ---------------------------------------------------------- accumulate ----
// Warp-per-point: lane l loads dims l and l+32 (two coalesced 128B LDG.32
// sweeps per point, streaming/evict-first), butterfly-reduces ||x||^2, and
// does two conflict-free shared atomicAdds (bank = dim mod 32). Block-private
// smem accumulators are flushed to global with one atomicAdd pass at the end.
// 4-point unroll front-batches 8 independent point-loads for MLP.
__global__ __launch_bounds__(256) void dbi_accum_kernel(
    const float* __restrict__ pts,
    const void*  __restrict__ cl_raw,
    int n)
{
    __shared__ float s[NACC];
    for (int i = threadIdx.x; i < NACC; i += blockDim.x) s[i] = 0.0f;
    __syncthreads();

    const int id64 = g_id64;                       // uniform
    const long long* cl64 = (const long long*)cl_raw;
    const int*       cl32 = (const int*)cl_raw;

    const int lane   = threadIdx.x & 31;
    const int warp   = (blockIdx.x * blockDim.x + threadIdx.x) >> 5;
    const int nwarps = (gridDim.x * blockDim.x) >> 5;

    #define LOAD_ID(p) (id64 ? (int)cl64[(p)] : cl32[(p)])

    int p = warp;
    for (; p + 3 * nwarps < n; p += 4 * nwarps) {
        const int p0 = p, p1 = p + nwarps, p2 = p + 2 * nwarps, p3 = p + 3 * nwarps;
        // Front-batch all loads (ids + 8 data LDGs) for memory-level parallelism.
        const int c0 = LOAD_ID(p0);
        const int c1 = LOAD_ID(p1);
        const int c2 = LOAD_ID(p2);
        const int c3 = LOAD_ID(p3);
        const float* r0 = pts + (size_t)p0 * DF;
        const float* r1 = pts + (size_t)p1 * DF;
        const float* r2 = pts + (size_t)p2 * DF;
        const float* r3 = pts + (size_t)p3 * DF;
        float a0 = __ldcs(r0 + lane), a1 = __ldcs(r0 + lane + 32);
        float b0 = __ldcs(r1 + lane), b1 = __ldcs(r1 + lane + 32);
        float e0 = __ldcs(r2 + lane), e1 = __ldcs(r2 + lane + 32);
        float f0 = __ldcs(r3 + lane), f1 = __ldcs(r3 + lane + 32);

        float sqa = a0 * a0 + a1 * a1;
        float sqb = b0 * b0 + b1 * b1;
        float sqe = e0 * e0 + e1 * e1;
        float sqf = f0 * f0 + f1 * f1;
        #pragma unroll
        for (int o = 16; o; o >>= 1) {
            sqa += __shfl_xor_sync(0xffffffffu, sqa, o);
            sqb += __shfl_xor_sync(0xffffffffu, sqb, o);
            sqe += __shfl_xor_sync(0xffffffffu, sqe, o);
            sqf += __shfl_xor_sync(0xffffffffu, sqf, o);
        }
        if ((unsigned)c0 < KC) {
            atomicAdd(&s[c0 * DF + lane],      a0);
            atomicAdd(&s[c0 * DF + lane + 32], a1);
            if (lane == 0) atomicAdd(&s[NSUM + c0], 1.0f);
            if (lane == 1) atomicAdd(&s[NSUM + KC + c0], sqa);
        }
        if ((unsigned)c1 < KC) {
            atomicAdd(&s[c1 * DF + lane],      b0);
            atomicAdd(&s[c1 * DF + lane + 32], b1);
            if (lane == 0) atomicAdd(&s[NSUM + c1], 1.0f);
            if (lane == 1) atomicAdd(&s[NSUM + KC + c1], sqb);
        }
        if ((unsigned)c2 < KC) {
            atomicAdd(&s[c2 * DF + lane],      e0);
            atomicAdd(&s[c2 * DF + lane + 32], e1);
            if (lane == 0) atomicAdd(&s[NSUM + c2], 1.0f);
            if (lane == 1) atomicAdd(&s[NSUM + KC + c2], sqe);
        }
        if ((unsigned)c3 < KC) {
            atomicAdd(&s[c3 * DF + lane],      f0);
            atomicAdd(&s[c3 * DF + lane + 32], f1);
            if (lane == 0) atomicAdd(&s[NSUM + c3], 1.0f);
            if (lane == 1) atomicAdd(&s[NSUM + KC + c3], sqf);
        }
    }
    for (; p < n; p += nwarps) {
        const int c = LOAD_ID(p);
        const float* r0 = pts + (size_t)p * DF;
        float a0 = __ldcs(r0 + lane), a1 = __ldcs(r0 + lane + 32);
        float sqa = a0 * a0 + a1 * a1;
        #pragma unroll
        for (int o = 16; o; o >>= 1) sqa += __shfl_xor_sync(0xffffffffu, sqa, o);
        if ((unsigned)c < KC) {
            atomicAdd(&s[c * DF + lane],      a0);
            atomicAdd(&s[c * DF + lane + 32], a1);
            if (lane == 0) atomicAdd(&s[NSUM + c], 1.0f);
            if (lane == 1) atomicAdd(&s[NSUM + KC + c], sqa);
        }
    }
    #undef LOAD_ID

    __syncthreads();
    for (int i = threadIdx.x; i < NACC; i += blockDim.x) {
        float v = s[i];
        if (v != 0.0f) atomicAdd(&g_acc[i], v);
    }
}

// ------------------------------------------------------------ finalize ----
__global__ __launch_bounds__(128) void dbi_final_kernel(float* __restrict__ out) {
    __shared__ float A[KC][DF];
    __shared__ float Si[KC];
    __shared__ float rowmax[KC];
    const int tid = threadIdx.x;

    // centroids: A = (0.001 + Sx) / (1 + n)
    for (int i = tid; i < NSUM; i += blockDim.x) {
        int c = i / DF, d = i - c * DF;
        float cnt = 1.0f + g_acc[NSUM + c];
        A[c][d] = (0.001f + g_acc[i]) / cnt;
    }
    __syncthreads();

    // Si via expansion: Sum||x-A||^2 = Sxx - 2 A.Sx + n ||A||^2
    if (tid < KC) {
        const int c = tid;
        float nk  = g_acc[NSUM + c];
        float cnt = 1.0f + nk;
        float sxx = g_acc[NSUM + KC + c];
        float dot = 0.0f, a2 = 0.0f;
        #pragma unroll 8
        for (int d = 0; d < DF; d++) {
            float a = A[c][d];
            dot += a * g_acc[c * DF + d];
            a2  += a * a;
        }
        float sq = sxx - 2.0f * dot + nk * a2;
        Si[c] = sqrtf((0.001f + sq) / cnt);
    }
    __syncthreads();

    // Rij row maxes
    if (tid < KC) {
        const int i = tid;
        float m = 0.0f;
        for (int j = 0; j < KC; j++) {
            if (j == i) continue;
            float ss = 0.0f;
            #pragma unroll 8
            for (int d = 0; d < DF; d++) {
                float df = A[i][d] - A[j][d];
                ss += df * df;
            }
            float r = (Si[i] + Si[j]) * rsqrtf(ss);
            m = fmaxf(m, r);
        }
        rowmax[i] = m;
    }
    __syncthreads();

    if (tid == 0) {
        float sum = 0.0f;
        for (int c = 0; c < KC; c++) sum += rowmax[c];
        out[0] = sum / (float)KC;
    }
}

// -------------------------------------------------------------- launch ----
extern "C" void kernel_launch(void* const* d_in, const int* in_sizes, int n_in,
                              void* d_out, int out_size) {
    // Resolve binding from element counts: data_points has DF=64x the
    // elements of clustering. Robust to either metadata ordering.
    const long long s0 = in_sizes[0];
    const long long s1 = (n_in > 1) ? in_sizes[1] : 0;

    const float* pts;
    const void*  cl;
    int n;
    if (s0 == 64 * s1) {          // d_in[0]=data_points, d_in[1]=clustering
        pts = (const float*)d_in[0];
        cl  = d_in[1];
        n   = (int)s1;
    } else {                      // swapped order
        pts = (const float*)d_in[1];
        cl  = d_in[0];
        n   = (int)s0;
    }

    // Probe reads u32[2k+1] for k < nprobe. Under the int32 interpretation
    // that touches 2*nprobe ids, so cap nprobe at n/2 to stay in-bounds
    // for either dtype.
    int nprobe_cap = n / 2 < 128 ? n / 2 : 128;
    dbi_init_kernel<<<(NACC + 255) / 256, 256>>>((const unsigned int*)cl, nprobe_cap);
    dbi_accum_kernel<<<1184, 256>>>(pts, cl, n);
    dbi_final_kernel<<<1, 128>>>((float*)d_out);
}